// round 15
// baseline (speedup 1.0000x reference)
#include <cuda_runtime.h>
#include <math.h>

#define A_N 32768
#define B_N 32
#define G_N 50
#define C_N 22
#define TILE_A 512
#define TILES (A_N / TILE_A)   // 64
#define NW 32
#define HPAD 257
#define HSEG (2 * HPAD)
#define CAND_CAP 4096
#define TOPK_DYN ((NW * HSEG + CAND_CAP) * 4)   // 82176 B dynamic
#define CONF_TILE_BYTES (256 * C_N * 4)          // 22528

// ---------------- persistent scratch (zero-init at load; last block re-zeros) --
__device__ unsigned long long g_best_pack[B_N * G_N];  // (iou_prefix<<32)|(~a)
__device__ uchar2 g_matchc[B_N * A_N];     // (passed flag, best gt idx); forced stamped
__device__ float  g_mining[B_N * A_N];     // bg_loss for negatives, -1.0f for positives
__device__ int    g_row_done[B_N];
__device__ int    g_num_pos_row[B_N];
__device__ double g_loc_sum;
__device__ double g_ce_sum;
__device__ float  g_row_topk[B_N];
__device__ unsigned g_done;

// ---------------- helpers ----------------
__device__ __forceinline__ float sl1(float d) {
    float ad = fabsf(d);
    return (ad < 1.0f) ? 0.5f * ad * ad : ad - 0.5f;
}
__device__ __forceinline__ float warp_sum_f(float v) {
    #pragma unroll
    for (int o = 16; o; o >>= 1) v += __shfl_down_sync(0xffffffffu, v, o);
    return v;
}
__device__ __forceinline__ int warp_sum_i(int v) {
    #pragma unroll
    for (int o = 16; o; o >>= 1) v += __shfl_down_sync(0xffffffffu, v, o);
    return v;
}
__device__ __forceinline__ float ex2f(float x) {
    float r; asm("ex2.approx.f32 %0, %1;" : "=f"(r) : "f"(x)); return r;
}
__device__ __forceinline__ float lg2f(float x) {
    float r; asm("lg2.approx.f32 %0, %1;" : "=f"(r) : "f"(x)); return r;
}
__device__ __forceinline__ float rcpf(float x) {
    float r; asm("rcp.approx.f32 %0, %1;" : "=f"(r) : "f"(x)); return r;
}
__device__ __forceinline__ unsigned smem_u32(const void* p) {
    unsigned r;
    asm("{ .reg .u64 t; cvta.to.shared.u64 t, %1; cvt.u32.u64 %0, t; }" : "=r"(r) : "l"(p));
    return r;
}

// ---------------- K1: matching, 2 anchors/thread, packed-key argmax ----------
__global__ void __launch_bounds__(256) k_match(const float* __restrict__ gts,
                                               const int* __restrict__ counts,
                                               const float* __restrict__ anchors) {
    int tile = blockIdx.x, b = blockIdx.y;
    int tid = threadIdx.x;
    int lane = tid & 31;

    __shared__ float4 s_box[G_N];
    __shared__ float  s_areaG[G_N];
    __shared__ unsigned s_fa[G_N];
    __shared__ int s_cnt;
    __shared__ int s_last;
    if (tid == 0) s_cnt = counts[b];
    if (tid < G_N) {
        const float* gp = gts + (size_t)(b * G_N + tid) * 5;
        float x0 = gp[0], y0 = gp[1], x1 = gp[2], y1 = gp[3];
        s_box[tid] = make_float4(x0, y0, x1, y1);
        s_areaG[tid] = (x1 - x0) * (y1 - y0);
    }
    __syncthreads();
    int cnt = s_cnt;

    int base = tile * TILE_A;
    float4 ab[2]; float sA[2];
    unsigned bkey[2];                       // (iou&~63)|(63-g): first-max over g
    #pragma unroll
    for (int k = 0; k < 2; k++) {
        ab[k] = ((const float4*)anchors)[base + tid + k * 256];
        sA[k] = (ab[k].z - ab[k].x) * (ab[k].w - ab[k].y) + 1e-5f;
        bkey[k] = 0u;
    }

    for (int g = 0; g < cnt; g++) {
        float4 gb = s_box[g];
        float aG = s_areaG[g];
        unsigned gk = (unsigned)(63 - g);
        unsigned lkey = 0u;                 // (iou&~1)|(1-k): smaller k wins ties
        #pragma unroll
        for (int k = 0; k < 2; k++) {
            float ltx = fmaxf(gb.x, ab[k].x), lty = fmaxf(gb.y, ab[k].y);
            float rbx = fminf(gb.z, ab[k].z), rby = fminf(gb.w, ab[k].w);
            float w = fmaxf(rbx - ltx, 0.0f), h = fmaxf(rby - lty, 0.0f);
            float inter = w * h;
            float v = inter * rcpf((aG + sA[k]) - inter);       // approx key
            unsigned u = __float_as_uint(v);
            unsigned kb = (u & 0xFFFFFFC0u) | gk;
            bkey[k] = (kb > bkey[k]) ? kb : bkey[k];            // UIMNMX
            unsigned kl = (u & 0xFFFFFFFEu) | (unsigned)(1 - k);
            lkey = (kl > lkey) ? kl : lkey;                     // UIMNMX
        }
        // warp argmax over anchors: max key, then min tid among ties
        unsigned wkey = __reduce_max_sync(0xffffffffu, lkey);
        unsigned cand = (lkey == wkey) ? (unsigned)tid : 0xFFFFFFFFu;
        unsigned mint = __reduce_min_sync(0xffffffffu, cand);
        if (lane == 0) {
            unsigned a_win = (unsigned)base + ((1u - (wkey & 1u)) << 8) + mint;
            atomicMax(&g_best_pack[b * G_N + g],
                      ((unsigned long long)(wkey & 0xFFFFFFFEu) << 32)
                      | (unsigned)(0xFFFFFFFFu - a_win));
        }
    }

    // exact IEEE IoU threshold decision for the winning gt; store 2 bytes
    #pragma unroll
    for (int k = 0; k < 2; k++) {
        int bid = 63 - (int)(bkey[k] & 63u);
        float4 gb = s_box[bid];
        float aG = s_areaG[bid];
        float ltx = fmaxf(gb.x, ab[k].x), lty = fmaxf(gb.y, ab[k].y);
        float rbx = fminf(gb.z, ab[k].z), rby = fminf(gb.w, ab[k].w);
        float w = fmaxf(rbx - ltx, 0.0f), h = fmaxf(rby - lty, 0.0f);
        float inter = w * h;
        float exact = inter / ((aG + sA[k]) - inter);           // exact IEEE division
        size_t id = (size_t)b * A_N + base + tid + k * 256;
        g_matchc[id] = make_uchar2(exact >= 0.5f ? 1 : 0, (unsigned char)bid);
    }

    // last block of this row stamps forced matches (ascending g, last wins)
    __threadfence();
    __syncthreads();
    if (tid == 0) {
        int old = atomicAdd(&g_row_done[b], 1);
        s_last = (old == TILES - 1) ? 1 : 0;
    }
    __syncthreads();
    if (s_last) {
        if (tid < cnt) {
            unsigned long long p = atomicMax(&g_best_pack[b * G_N + tid], 0ull); // atomic read
            s_fa[tid] = 0xFFFFFFFFu - (unsigned)(p & 0xFFFFFFFFull);
        }
        __syncthreads();
        if (tid == 0) {
            for (int g = 0; g < cnt; g++)
                g_matchc[(size_t)b * A_N + s_fa[g]] = make_uchar2(1, (unsigned char)g);
        }
    }
}

// ---------------- K2: TMA-staged log_softmax + loc loss + pos ce -------------
__global__ void __launch_bounds__(256) k_main(const float* __restrict__ conf,
                                              const float* __restrict__ pred,
                                              const float* __restrict__ gts,
                                              const float* __restrict__ anchors) {
    int b = blockIdx.y;
    int tid = threadIdx.x;
    int a = blockIdx.x * 256 + tid;

    __shared__ alignas(16) float s_conf[256 * C_N];   // 22528 B
    __shared__ float s_gts[G_N * 5];
    __shared__ unsigned long long s_mbar;

    unsigned mbar = smem_u32(&s_mbar);
    if (tid == 0)
        asm volatile("mbarrier.init.shared.b64 [%0], %1;" :: "r"(mbar), "r"(1) : "memory");
    __syncthreads();
    if (tid == 0) {
        asm volatile("mbarrier.arrive.expect_tx.shared.b64 _, [%0], %1;"
                     :: "r"(mbar), "r"((unsigned)CONF_TILE_BYTES) : "memory");
        const float* src = conf + ((size_t)b * A_N + (size_t)blockIdx.x * 256) * C_N;
        asm volatile("cp.async.bulk.shared::cta.global.mbarrier::complete_tx::bytes "
                     "[%0], [%1], %2, [%3];"
                     :: "r"(smem_u32(s_conf)), "l"(src),
                        "r"((unsigned)CONF_TILE_BYTES), "r"(mbar) : "memory");
    }

    for (int i = tid; i < G_N * 5; i += 256)
        s_gts[i] = gts[(size_t)b * G_N * 5 + i];

    size_t idx = (size_t)b * A_N + a;
    uchar2 mt = g_matchc[idx];
    int passed = mt.x;
    int bidx = mt.y;
    __syncthreads();

    int label = passed ? (int)s_gts[bidx * 5 + 4] : 0;
    int is_pos = (label > 0);

    float loc_partial = 0.0f;
    if (is_pos) {
        float4 ab = ((const float4*)anchors)[a];
        float gx0 = s_gts[bidx*5+0], gy0 = s_gts[bidx*5+1];
        float gx1 = s_gts[bidx*5+2], gy1 = s_gts[bidx*5+3];
        float gcx = (gx0 + gx1) * 0.5f, gcy = (gy0 + gy1) * 0.5f;
        float gw  = gx1 - gx0,          gh  = gy1 - gy0;
        float acx = (ab.x + ab.z) * 0.5f, acy = (ab.y + ab.w) * 0.5f;
        float aw  = ab.z - ab.x,          ah  = ab.w - ab.y;
        float t0 = (gcx - acx) / aw / 0.1f;
        float t1 = (gcy - acy) / ah / 0.1f;
        float t2 = logf(fmaxf(gw / aw, 1e-8f)) / 0.2f;
        float t3 = logf(fmaxf(gh / ah, 1e-8f)) / 0.2f;
        float4 p = ((const float4*)pred)[idx];
        loc_partial = sl1(p.x - t0) + sl1(p.y - t1) + sl1(p.z - t2) + sl1(p.w - t3);
    }

    {
        unsigned done;
        asm volatile("{\n\t.reg .pred p;\n\t"
                     "mbarrier.try_wait.parity.shared.b64 p, [%1], %2;\n\t"
                     "selp.b32 %0, 1, 0, p;\n\t}"
                     : "=r"(done) : "r"(mbar), "r"(0u) : "memory");
        while (!done) {
            asm volatile("{\n\t.reg .pred p;\n\t"
                         "mbarrier.try_wait.parity.shared.b64 p, [%1], %2;\n\t"
                         "selp.b32 %0, 1, 0, p;\n\t}"
                         : "=r"(done) : "r"(mbar), "r"(0u) : "memory");
        }
    }

    const float L2E = 1.4426950408889634f;
    const float LN2 = 0.6931471805599453f;
    const float2* myc2 = (const float2*)(s_conf + tid * C_N);
    float2 v0 = myc2[0];
    float c0 = v0.x;
    float c0L = c0 * L2E;
    float S0 = 1.0f, S1 = ex2f(fmaf(v0.y, L2E, -c0L));
    #pragma unroll
    for (int i = 1; i < 11; i++) {
        float2 v = myc2[i];
        S0 += ex2f(fmaf(v.x, L2E, -c0L));
        S1 += ex2f(fmaf(v.y, L2E, -c0L));
    }
    float bg = lg2f(S0 + S1) * LN2;

    float ce_partial = 0.0f;
    if (is_pos) {
        float clb = s_conf[tid * C_N + label];
        ce_partial = (c0 - clb) + bg;
        g_mining[idx] = -1.0f;
    } else {
        g_mining[idx] = bg;
    }

    float wl = warp_sum_f(loc_partial);
    float wc = warp_sum_f(ce_partial);
    int   wp = warp_sum_i(is_pos);
    __shared__ float rl[8], rc[8];
    __shared__ int   rp[8];
    int lane = tid & 31, wid = tid >> 5;
    if (lane == 0) { rl[wid] = wl; rc[wid] = wc; rp[wid] = wp; }
    __syncthreads();
    if (wid == 0) {
        float bl = (lane < 8) ? rl[lane] : 0.0f;
        float bc = (lane < 8) ? rc[lane] : 0.0f;
        int   bp = (lane < 8) ? rp[lane] : 0;
        bl = warp_sum_f(bl); bc = warp_sum_f(bc); bp = warp_sum_i(bp);
        if (lane == 0) {
            if (bl != 0.0f) atomicAdd(&g_loc_sum, (double)bl);
            if (bc != 0.0f) atomicAdd(&g_ce_sum, (double)bc);
            if (bp != 0)    atomicAdd(&g_num_pos_row[b], bp);
        }
    }
}

// ---------------- K3: radix top-k, fused dual-histogram first pass ------------
__global__ void __launch_bounds__(1024) k_topk(float* __restrict__ out) {
    extern __shared__ unsigned sdyn_u[];
    unsigned* whist  = sdyn_u;
    unsigned* s_cand = sdyn_u + NW * HSEG;

    __shared__ unsigned suf[256];
    __shared__ unsigned s_sel;
    __shared__ int s_rem;
    __shared__ int s_ccnt;
    __shared__ float rs[32];
    __shared__ int   rg[32];
    __shared__ unsigned s_last;

    int b = blockIdx.x;
    int tid = threadIdx.x;
    int lane = tid & 31;
    int wid = tid >> 5;

    int npos = g_num_pos_row[b];
    int kk = min(3 * npos, A_N - npos);
    const float* mv = g_mining + (size_t)b * A_N;

    if (kk > 0) {
        for (int i = tid; i < NW * HSEG; i += 1024) whist[i] = 0u;
        __syncthreads();
        unsigned* hA = whist + wid * HSEG;
        unsigned* hB = hA + HPAD;
        for (int i = tid; i < A_N; i += 1024) {
            float v = mv[i];
            unsigned u = __float_as_uint(v);
            bool nonneg = (v >= 0.0f);
            unsigned b0 = u >> 24;
            unsigned key0 = nonneg ? b0 : 0x100u;
            unsigned p0 = __match_any_sync(0xFFFFFFFFu, key0);
            if (nonneg && lane == (__ffs(p0) - 1)) hA[b0] += __popc(p0);
            bool c2 = nonneg && (b0 == 0x40u);
            unsigned b1 = (u >> 16) & 255u;
            unsigned key1 = c2 ? b1 : 0x100u;
            unsigned p1 = __match_any_sync(0xFFFFFFFFu, key1);
            if (c2 && lane == (__ffs(p1) - 1)) hB[b1] += __popc(p1);
        }
        __syncthreads();

        int rem = kk;
        if (tid < 256) {
            unsigned s = 0u;
            #pragma unroll
            for (int w = 0; w < NW; w++) s += whist[w * HSEG + tid];
            suf[tid] = s;
        }
        __syncthreads();
        for (int off = 1; off < 256; off <<= 1) {
            unsigned v = 0;
            if (tid < 256) v = suf[tid] + ((tid + off < 256) ? suf[tid + off] : 0u);
            __syncthreads();
            if (tid < 256) suf[tid] = v;
            __syncthreads();
        }
        if (tid < 256) {
            unsigned below = (tid == 255) ? 0u : suf[tid + 1];
            if (suf[tid] >= (unsigned)rem && below < (unsigned)rem) {
                s_sel = (unsigned)tid;
                s_rem = rem - (int)below;
            }
        }
        __syncthreads();
        unsigned t0b = s_sel;
        rem = s_rem;
        __syncthreads();

        if (t0b != 0x40u) {
            for (int i = tid; i < NW * HSEG; i += 1024) {
                int off = i % HSEG;
                if (off >= HPAD) whist[i] = 0u;
            }
            __syncthreads();
            for (int i = tid; i < A_N; i += 1024) {
                float v = mv[i];
                unsigned u = __float_as_uint(v);
                bool act = (v >= 0.0f) && ((u >> 24) == t0b);
                unsigned b1 = (u >> 16) & 255u;
                unsigned key = act ? b1 : 0x100u;
                unsigned p1 = __match_any_sync(0xFFFFFFFFu, key);
                if (act && lane == (__ffs(p1) - 1)) hB[b1] += __popc(p1);
            }
            __syncthreads();
        }
        if (tid < 256) {
            unsigned s = 0u;
            #pragma unroll
            for (int w = 0; w < NW; w++) s += whist[w * HSEG + HPAD + tid];
            suf[tid] = s;
        }
        __syncthreads();
        for (int off = 1; off < 256; off <<= 1) {
            unsigned v = 0;
            if (tid < 256) v = suf[tid] + ((tid + off < 256) ? suf[tid + off] : 0u);
            __syncthreads();
            if (tid < 256) suf[tid] = v;
            __syncthreads();
        }
        if (tid < 256) {
            unsigned below = (tid == 255) ? 0u : suf[tid + 1];
            if (suf[tid] >= (unsigned)rem && below < (unsigned)rem) {
                s_sel = (unsigned)tid;
                s_rem = rem - (int)below;
            }
        }
        __syncthreads();
        unsigned prefix = (t0b << 24) | (s_sel << 16);
        rem = s_rem;
        __syncthreads();

        if (tid == 0) s_ccnt = 0;
        __syncthreads();
        unsigned p16 = prefix >> 16;
        float gt_sum = 0.0f; int gt_cnt = 0;
        for (int i = tid; i < A_N; i += 1024) {
            float v = mv[i];
            unsigned u = __float_as_uint(v);
            bool nonneg = (v >= 0.0f);
            unsigned hi = u >> 16;
            if (nonneg && hi > p16) { gt_sum += v; gt_cnt++; }
            bool iscand = nonneg && (hi == p16);
            unsigned bal = __ballot_sync(0xFFFFFFFFu, iscand);
            if (iscand) {
                int leader = __ffs(bal) - 1;
                int basep = 0;
                if (lane == leader) basep = atomicAdd(&s_ccnt, __popc(bal));
                basep = __shfl_sync(bal, basep, leader);
                int pos = basep + __popc(bal & ((1u << lane) - 1u));
                if (pos < CAND_CAP) s_cand[pos] = u;
            }
        }
        __syncthreads();
        int ccnt = s_ccnt;
        bool compacted = (ccnt <= CAND_CAP);
        int ccnt_pad = (ccnt + 1023) & ~1023;

        for (int round = 2; round < 4; round++) {
            int shift = 24 - round * 8;
            unsigned pmask = 0xFFFFFFFFu << (shift + 8);
            for (int i = tid; i < NW * HSEG; i += 1024) {
                int off = i % HSEG;
                if (off < HPAD) whist[i] = 0u;
            }
            __syncthreads();
            unsigned* myh = whist + wid * HSEG;
            if (compacted) {
                for (int i = tid; i < ccnt_pad; i += 1024) {
                    bool inb = (i < ccnt);
                    unsigned u = inb ? s_cand[i] : 0u;
                    bool act = inb && ((u & pmask) == prefix);
                    unsigned bin = (u >> shift) & 255u;
                    unsigned key = act ? bin : 0x100u;
                    unsigned peers = __match_any_sync(0xFFFFFFFFu, key);
                    if (act && lane == (__ffs(peers) - 1)) myh[bin] += __popc(peers);
                }
            } else {
                for (int i = tid; i < A_N; i += 1024) {
                    float v = mv[i];
                    unsigned u = __float_as_uint(v);
                    bool act = (v >= 0.0f) && ((u & pmask) == prefix);
                    unsigned bin = (u >> shift) & 255u;
                    unsigned key = act ? bin : 0x100u;
                    unsigned peers = __match_any_sync(0xFFFFFFFFu, key);
                    if (act && lane == (__ffs(peers) - 1)) myh[bin] += __popc(peers);
                }
            }
            __syncthreads();
            if (tid < 256) {
                unsigned s = 0u;
                #pragma unroll
                for (int w = 0; w < NW; w++) s += whist[w * HSEG + tid];
                suf[tid] = s;
            }
            __syncthreads();
            for (int off = 1; off < 256; off <<= 1) {
                unsigned v = 0;
                if (tid < 256) v = suf[tid] + ((tid + off < 256) ? suf[tid + off] : 0u);
                __syncthreads();
                if (tid < 256) suf[tid] = v;
                __syncthreads();
            }
            if (tid < 256) {
                unsigned below = (tid == 255) ? 0u : suf[tid + 1];
                if (suf[tid] >= (unsigned)rem && below < (unsigned)rem) {
                    s_sel = (unsigned)tid;
                    s_rem = rem - (int)below;
                }
            }
            __syncthreads();
            prefix |= (s_sel << shift);
            rem = s_rem;
            __syncthreads();
        }

        float Tf = __uint_as_float(prefix);
        float ssum; int cgt;
        if (compacted) {
            ssum = gt_sum; cgt = gt_cnt;
            for (int i = tid; i < ccnt; i += 1024) {
                unsigned u = s_cand[i];
                if (u > prefix) { ssum += __uint_as_float(u); cgt++; }
            }
        } else {
            ssum = 0.0f; cgt = 0;
            for (int i = tid; i < A_N; i += 1024) {
                float v = mv[i];
                if (v < 0.0f) continue;
                if (__float_as_uint(v) > prefix) { ssum += v; cgt++; }
            }
        }
        float ws = warp_sum_f(ssum);
        int   wg = warp_sum_i(cgt);
        if (lane == 0) { rs[wid] = ws; rg[wid] = wg; }
        __syncthreads();
        if (wid == 0) {
            float bs = rs[lane];
            int   bgc = rg[lane];
            bs = warp_sum_f(bs); bgc = warp_sum_i(bgc);
            if (lane == 0) g_row_topk[b] = bs + (float)(kk - bgc) * Tf;
        }
    } else {
        if (tid == 0) g_row_topk[b] = 0.0f;
    }

    __syncthreads();
    if (tid == 0) {
        __threadfence();
        unsigned old = atomicAdd(&g_done, 1u);
        s_last = (old == (unsigned)(B_N - 1)) ? 1u : 0u;
    }
    __syncthreads();
    if (s_last) {
        if (tid < 32) {
            int np = g_num_pos_row[tid];
            float tk = g_row_topk[tid];
            np = warp_sum_i(np);
            tk = warp_sum_f(tk);
            if (tid == 0) {
                double denom = fmax(1.0, (double)np) * 4.0;
                out[0] = (float)(g_loc_sum / denom);
                out[1] = (float)((g_ce_sum + (double)tk) / denom);
            }
        }
        for (int i = tid; i < B_N * G_N; i += 1024) g_best_pack[i] = 0ull;
        if (tid < B_N) { g_num_pos_row[tid] = 0; g_row_done[tid] = 0; }
        if (tid == 0) { g_loc_sum = 0.0; g_ce_sum = 0.0; g_done = 0u; }
    }
}

extern "C" void kernel_launch(void* const* d_in, const int* in_sizes, int n_in,
                              void* d_out, int out_size) {
    const float* conf    = (const float*)d_in[0];
    const float* pred    = (const float*)d_in[1];
    const float* gts     = (const float*)d_in[2];
    const int*   counts  = (const int*)d_in[3];
    const float* anchors = (const float*)d_in[4];
    float* out = (float*)d_out;

    cudaFuncSetAttribute(k_topk, cudaFuncAttributeMaxDynamicSharedMemorySize, TOPK_DYN);

    k_match<<<dim3(TILES, B_N), 256>>>(gts, counts, anchors);
    k_main<<<dim3(A_N / 256, B_N), 256>>>(conf, pred, gts, anchors);
    k_topk<<<B_N, 1024, TOPK_DYN>>>(out);
}

// round 16
// speedup vs baseline: 1.0729x; 1.0729x over previous
#include <cuda_runtime.h>
#include <math.h>

#define A_N 32768
#define B_N 32
#define G_N 50
#define C_N 22
#define TILE_A 1024
#define TILES (A_N / TILE_A)   // 32
#define NW 32
#define HPAD 257
#define HSEG (2 * HPAD)
#define CAND_CAP 4096
#define TOPK_DYN ((NW * HSEG + CAND_CAP) * 4)   // 82176 B dynamic
#define CONF_TILE_BYTES (256 * C_N * 4)          // 22528

// ---------------- persistent scratch (zero-init at load; last block re-zeros) --
__device__ unsigned long long g_best_pack[B_N * G_N];  // (key&~3)<<32 | (~a)
__device__ uchar2 g_matchc[B_N * A_N];     // (passed flag, best gt idx); forced stamped
__device__ float  g_mining[B_N * A_N];     // bg_loss for negatives, -1.0f for positives
__device__ int    g_row_done[B_N];
__device__ int    g_num_pos_row[B_N];
__device__ double g_loc_sum;
__device__ double g_ce_sum;
__device__ float  g_row_topk[B_N];
__device__ unsigned g_done;

// ---------------- helpers ----------------
__device__ __forceinline__ float sl1(float d) {
    float ad = fabsf(d);
    return (ad < 1.0f) ? 0.5f * ad * ad : ad - 0.5f;
}
__device__ __forceinline__ float warp_sum_f(float v) {
    #pragma unroll
    for (int o = 16; o; o >>= 1) v += __shfl_down_sync(0xffffffffu, v, o);
    return v;
}
__device__ __forceinline__ int warp_sum_i(int v) {
    #pragma unroll
    for (int o = 16; o; o >>= 1) v += __shfl_down_sync(0xffffffffu, v, o);
    return v;
}
__device__ __forceinline__ float ex2f(float x) {
    float r; asm("ex2.approx.f32 %0, %1;" : "=f"(r) : "f"(x)); return r;
}
__device__ __forceinline__ float lg2f(float x) {
    float r; asm("lg2.approx.f32 %0, %1;" : "=f"(r) : "f"(x)); return r;
}
__device__ __forceinline__ float rcpf(float x) {
    float r; asm("rcp.approx.f32 %0, %1;" : "=f"(r) : "f"(x)); return r;
}
__device__ __forceinline__ unsigned smem_u32(const void* p) {
    unsigned r;
    asm("{ .reg .u64 t; cvta.to.shared.u64 t, %1; cvt.u32.u64 %0, t; }" : "=r"(r) : "l"(p));
    return r;
}

// ---------------- K1: matching, 4 anchors/thread, packed-key argmax ----------
__global__ void __launch_bounds__(256) k_match(const float* __restrict__ gts,
                                               const int* __restrict__ counts,
                                               const float* __restrict__ anchors) {
    int tile = blockIdx.x, b = blockIdx.y;
    int tid = threadIdx.x;
    int lane = tid & 31;

    __shared__ float4 s_box[G_N];
    __shared__ float  s_areaG[G_N];
    __shared__ unsigned s_fa[G_N];
    __shared__ int s_cnt;
    __shared__ int s_last;
    if (tid == 0) s_cnt = counts[b];
    if (tid < G_N) {
        const float* gp = gts + (size_t)(b * G_N + tid) * 5;
        float x0 = gp[0], y0 = gp[1], x1 = gp[2], y1 = gp[3];
        s_box[tid] = make_float4(x0, y0, x1, y1);
        s_areaG[tid] = (x1 - x0) * (y1 - y0);
    }
    __syncthreads();
    int cnt = s_cnt;

    int base = tile * TILE_A;
    float4 ab[4]; float sA[4];
    unsigned bkey[4];                       // (u&~63)|(63-g): first-max over g
    #pragma unroll
    for (int k = 0; k < 4; k++) {
        ab[k] = ((const float4*)anchors)[base + tid + k * 256];
        sA[k] = (ab[k].z - ab[k].x) * (ab[k].w - ab[k].y) + 1e-5f;
        bkey[k] = 0u;
    }

    for (int g = 0; g < cnt; g++) {
        float4 gb = s_box[g];
        float aG = s_areaG[g];
        unsigned gk = (unsigned)(63 - g);
        unsigned lkey = 0u;                 // (u&~3)|(3-k): smaller k wins ties
        #pragma unroll
        for (int k = 0; k < 4; k++) {
            float ltx = fmaxf(gb.x, ab[k].x), lty = fmaxf(gb.y, ab[k].y);
            float rbx = fminf(gb.z, ab[k].z), rby = fminf(gb.w, ab[k].w);
            float w = fmaxf(rbx - ltx, 0.0f), h = fmaxf(rby - lty, 0.0f);
            float inter = w * h;
            float v = inter * rcpf((aG + sA[k]) - inter);       // approx key
            unsigned u = __float_as_uint(v);
            unsigned kb = (u & 0xFFFFFFC0u) | gk;
            bkey[k] = (kb > bkey[k]) ? kb : bkey[k];            // UIMNMX
            unsigned kl = (u & 0xFFFFFFFCu) | (unsigned)(3 - k);
            lkey = (kl > lkey) ? kl : lkey;                     // UIMNMX
        }
        // warp argmax over anchors: max key, then min tid among key-ties
        unsigned wkey = __reduce_max_sync(0xffffffffu, lkey);
        unsigned cand = (lkey == wkey) ? (unsigned)tid : 0xFFFFFFFFu;
        unsigned mint = __reduce_min_sync(0xffffffffu, cand);
        if (lane == 0) {
            unsigned a_win = (unsigned)base + ((3u - (wkey & 3u)) << 8) + mint;
            atomicMax(&g_best_pack[b * G_N + g],
                      ((unsigned long long)(wkey & 0xFFFFFFFCu) << 32)
                      | (unsigned)(0xFFFFFFFFu - a_win));
        }
    }

    // exact IEEE IoU threshold decision for the winning gt; store 2 bytes
    #pragma unroll
    for (int k = 0; k < 4; k++) {
        int bid = 63 - (int)(bkey[k] & 63u);
        float4 gb = s_box[bid];
        float aG = s_areaG[bid];
        float ltx = fmaxf(gb.x, ab[k].x), lty = fmaxf(gb.y, ab[k].y);
        float rbx = fminf(gb.z, ab[k].z), rby = fminf(gb.w, ab[k].w);
        float w = fmaxf(rbx - ltx, 0.0f), h = fmaxf(rby - lty, 0.0f);
        float inter = w * h;
        float exact = inter / ((aG + sA[k]) - inter);           // exact IEEE division
        size_t id = (size_t)b * A_N + base + tid + k * 256;
        g_matchc[id] = make_uchar2(exact >= 0.5f ? 1 : 0, (unsigned char)bid);
    }

    // last block of this row stamps forced matches (ascending g, last wins)
    __threadfence();
    __syncthreads();
    if (tid == 0) {
        int old = atomicAdd(&g_row_done[b], 1);
        s_last = (old == TILES - 1) ? 1 : 0;
    }
    __syncthreads();
    if (s_last) {
        if (tid < cnt) {
            unsigned long long p = atomicMax(&g_best_pack[b * G_N + tid], 0ull); // atomic read
            s_fa[tid] = 0xFFFFFFFFu - (unsigned)(p & 0xFFFFFFFFull);
        }
        __syncthreads();
        if (tid == 0) {
            for (int g = 0; g < cnt; g++)
                g_matchc[(size_t)b * A_N + s_fa[g]] = make_uchar2(1, (unsigned char)g);
        }
    }
}

// ---------------- K2: TMA-staged log_softmax + loc loss + pos ce -------------
__global__ void __launch_bounds__(256) k_main(const float* __restrict__ conf,
                                              const float* __restrict__ pred,
                                              const float* __restrict__ gts,
                                              const float* __restrict__ anchors) {
    int b = blockIdx.y;
    int tid = threadIdx.x;
    int a = blockIdx.x * 256 + tid;

    __shared__ alignas(16) float s_conf[256 * C_N];   // 22528 B
    __shared__ float s_gts[G_N * 5];
    __shared__ unsigned long long s_mbar;

    unsigned mbar = smem_u32(&s_mbar);
    if (tid == 0)
        asm volatile("mbarrier.init.shared.b64 [%0], %1;" :: "r"(mbar), "r"(1) : "memory");
    __syncthreads();
    if (tid == 0) {
        asm volatile("mbarrier.arrive.expect_tx.shared.b64 _, [%0], %1;"
                     :: "r"(mbar), "r"((unsigned)CONF_TILE_BYTES) : "memory");
        const float* src = conf + ((size_t)b * A_N + (size_t)blockIdx.x * 256) * C_N;
        asm volatile("cp.async.bulk.shared::cta.global.mbarrier::complete_tx::bytes "
                     "[%0], [%1], %2, [%3];"
                     :: "r"(smem_u32(s_conf)), "l"(src),
                        "r"((unsigned)CONF_TILE_BYTES), "r"(mbar) : "memory");
    }

    for (int i = tid; i < G_N * 5; i += 256)
        s_gts[i] = gts[(size_t)b * G_N * 5 + i];

    size_t idx = (size_t)b * A_N + a;
    uchar2 mt = g_matchc[idx];
    int passed = mt.x;
    int bidx = mt.y;
    __syncthreads();

    int label = passed ? (int)s_gts[bidx * 5 + 4] : 0;
    int is_pos = (label > 0);

    float loc_partial = 0.0f;
    if (is_pos) {
        float4 ab = ((const float4*)anchors)[a];
        float gx0 = s_gts[bidx*5+0], gy0 = s_gts[bidx*5+1];
        float gx1 = s_gts[bidx*5+2], gy1 = s_gts[bidx*5+3];
        float gcx = (gx0 + gx1) * 0.5f, gcy = (gy0 + gy1) * 0.5f;
        float gw  = gx1 - gx0,          gh  = gy1 - gy0;
        float acx = (ab.x + ab.z) * 0.5f, acy = (ab.y + ab.w) * 0.5f;
        float aw  = ab.z - ab.x,          ah  = ab.w - ab.y;
        float t0 = (gcx - acx) / aw / 0.1f;
        float t1 = (gcy - acy) / ah / 0.1f;
        float t2 = logf(fmaxf(gw / aw, 1e-8f)) / 0.2f;
        float t3 = logf(fmaxf(gh / ah, 1e-8f)) / 0.2f;
        float4 p = ((const float4*)pred)[idx];
        loc_partial = sl1(p.x - t0) + sl1(p.y - t1) + sl1(p.z - t2) + sl1(p.w - t3);
    }

    {
        unsigned done;
        asm volatile("{\n\t.reg .pred p;\n\t"
                     "mbarrier.try_wait.parity.shared.b64 p, [%1], %2;\n\t"
                     "selp.b32 %0, 1, 0, p;\n\t}"
                     : "=r"(done) : "r"(mbar), "r"(0u) : "memory");
        while (!done) {
            asm volatile("{\n\t.reg .pred p;\n\t"
                         "mbarrier.try_wait.parity.shared.b64 p, [%1], %2;\n\t"
                         "selp.b32 %0, 1, 0, p;\n\t}"
                         : "=r"(done) : "r"(mbar), "r"(0u) : "memory");
        }
    }

    const float L2E = 1.4426950408889634f;
    const float LN2 = 0.6931471805599453f;
    const float2* myc2 = (const float2*)(s_conf + tid * C_N);
    float2 v0 = myc2[0];
    float c0 = v0.x;
    float c0L = c0 * L2E;
    float S0 = 1.0f, S1 = ex2f(fmaf(v0.y, L2E, -c0L));
    #pragma unroll
    for (int i = 1; i < 11; i++) {
        float2 v = myc2[i];
        S0 += ex2f(fmaf(v.x, L2E, -c0L));
        S1 += ex2f(fmaf(v.y, L2E, -c0L));
    }
    float bg = lg2f(S0 + S1) * LN2;

    float ce_partial = 0.0f;
    if (is_pos) {
        float clb = s_conf[tid * C_N + label];
        ce_partial = (c0 - clb) + bg;
        g_mining[idx] = -1.0f;
    } else {
        g_mining[idx] = bg;
    }

    float wl = warp_sum_f(loc_partial);
    float wc = warp_sum_f(ce_partial);
    int   wp = warp_sum_i(is_pos);
    __shared__ float rl[8], rc[8];
    __shared__ int   rp[8];
    int lane = tid & 31, wid = tid >> 5;
    if (lane == 0) { rl[wid] = wl; rc[wid] = wc; rp[wid] = wp; }
    __syncthreads();
    if (wid == 0) {
        float bl = (lane < 8) ? rl[lane] : 0.0f;
        float bc = (lane < 8) ? rc[lane] : 0.0f;
        int   bp = (lane < 8) ? rp[lane] : 0;
        bl = warp_sum_f(bl); bc = warp_sum_f(bc); bp = warp_sum_i(bp);
        if (lane == 0) {
            if (bl != 0.0f) atomicAdd(&g_loc_sum, (double)bl);
            if (bc != 0.0f) atomicAdd(&g_ce_sum, (double)bc);
            if (bp != 0)    atomicAdd(&g_num_pos_row[b], bp);
        }
    }
}

// ---------------- K3: radix top-k, fused dual-histogram first pass ------------
__global__ void __launch_bounds__(1024) k_topk(float* __restrict__ out) {
    extern __shared__ unsigned sdyn_u[];
    unsigned* whist  = sdyn_u;
    unsigned* s_cand = sdyn_u + NW * HSEG;

    __shared__ unsigned suf[256];
    __shared__ unsigned s_sel;
    __shared__ int s_rem;
    __shared__ int s_ccnt;
    __shared__ float rs[32];
    __shared__ int   rg[32];
    __shared__ unsigned s_last;

    int b = blockIdx.x;
    int tid = threadIdx.x;
    int lane = tid & 31;
    int wid = tid >> 5;

    int npos = g_num_pos_row[b];
    int kk = min(3 * npos, A_N - npos);
    const float* mv = g_mining + (size_t)b * A_N;

    if (kk > 0) {
        // pass 1 (float4): histA(byte0) + histB(byte1 | byte0==0x40) in one scan
        for (int i = tid; i < NW * HSEG; i += 1024) whist[i] = 0u;
        __syncthreads();
        unsigned* hA = whist + wid * HSEG;
        unsigned* hB = hA + HPAD;
        const float4* mv4 = (const float4*)mv;
        for (int i = tid; i < A_N / 4; i += 1024) {
            float4 q = mv4[i];
            float vv[4] = {q.x, q.y, q.z, q.w};
            #pragma unroll
            for (int c = 0; c < 4; c++) {
                float v = vv[c];
                unsigned u = __float_as_uint(v);
                bool nonneg = (v >= 0.0f);
                unsigned b0 = u >> 24;
                unsigned key0 = nonneg ? b0 : 0x100u;
                unsigned p0 = __match_any_sync(0xFFFFFFFFu, key0);
                if (nonneg && lane == (__ffs(p0) - 1)) hA[b0] += __popc(p0);
                bool c2 = nonneg && (b0 == 0x40u);
                unsigned b1 = (u >> 16) & 255u;
                unsigned key1 = c2 ? b1 : 0x100u;
                unsigned p1 = __match_any_sync(0xFFFFFFFFu, key1);
                if (c2 && lane == (__ffs(p1) - 1)) hB[b1] += __popc(p1);
            }
        }
        __syncthreads();

        int rem = kk;
        if (tid < 256) {
            unsigned s = 0u;
            #pragma unroll
            for (int w = 0; w < NW; w++) s += whist[w * HSEG + tid];
            suf[tid] = s;
        }
        __syncthreads();
        for (int off = 1; off < 256; off <<= 1) {
            unsigned v = 0;
            if (tid < 256) v = suf[tid] + ((tid + off < 256) ? suf[tid + off] : 0u);
            __syncthreads();
            if (tid < 256) suf[tid] = v;
            __syncthreads();
        }
        if (tid < 256) {
            unsigned below = (tid == 255) ? 0u : suf[tid + 1];
            if (suf[tid] >= (unsigned)rem && below < (unsigned)rem) {
                s_sel = (unsigned)tid;
                s_rem = rem - (int)below;
            }
        }
        __syncthreads();
        unsigned t0b = s_sel;
        rem = s_rem;
        __syncthreads();

        if (t0b != 0x40u) {
            for (int i = tid; i < NW * HSEG; i += 1024) {
                int off = i % HSEG;
                if (off >= HPAD) whist[i] = 0u;
            }
            __syncthreads();
            for (int i = tid; i < A_N; i += 1024) {
                float v = mv[i];
                unsigned u = __float_as_uint(v);
                bool act = (v >= 0.0f) && ((u >> 24) == t0b);
                unsigned b1 = (u >> 16) & 255u;
                unsigned key = act ? b1 : 0x100u;
                unsigned p1 = __match_any_sync(0xFFFFFFFFu, key);
                if (act && lane == (__ffs(p1) - 1)) hB[b1] += __popc(p1);
            }
            __syncthreads();
        }
        if (tid < 256) {
            unsigned s = 0u;
            #pragma unroll
            for (int w = 0; w < NW; w++) s += whist[w * HSEG + HPAD + tid];
            suf[tid] = s;
        }
        __syncthreads();
        for (int off = 1; off < 256; off <<= 1) {
            unsigned v = 0;
            if (tid < 256) v = suf[tid] + ((tid + off < 256) ? suf[tid + off] : 0u);
            __syncthreads();
            if (tid < 256) suf[tid] = v;
            __syncthreads();
        }
        if (tid < 256) {
            unsigned below = (tid == 255) ? 0u : suf[tid + 1];
            if (suf[tid] >= (unsigned)rem && below < (unsigned)rem) {
                s_sel = (unsigned)tid;
                s_rem = rem - (int)below;
            }
        }
        __syncthreads();
        unsigned prefix = (t0b << 24) | (s_sel << 16);
        rem = s_rem;
        __syncthreads();

        if (tid == 0) s_ccnt = 0;
        __syncthreads();
        unsigned p16 = prefix >> 16;
        float gt_sum = 0.0f; int gt_cnt = 0;
        for (int i = tid; i < A_N; i += 1024) {
            float v = mv[i];
            unsigned u = __float_as_uint(v);
            bool nonneg = (v >= 0.0f);
            unsigned hi = u >> 16;
            if (nonneg && hi > p16) { gt_sum += v; gt_cnt++; }
            bool iscand = nonneg && (hi == p16);
            unsigned bal = __ballot_sync(0xFFFFFFFFu, iscand);
            if (iscand) {
                int leader = __ffs(bal) - 1;
                int basep = 0;
                if (lane == leader) basep = atomicAdd(&s_ccnt, __popc(bal));
                basep = __shfl_sync(bal, basep, leader);
                int pos = basep + __popc(bal & ((1u << lane) - 1u));
                if (pos < CAND_CAP) s_cand[pos] = u;
            }
        }
        __syncthreads();
        int ccnt = s_ccnt;
        bool compacted = (ccnt <= CAND_CAP);
        int ccnt_pad = (ccnt + 1023) & ~1023;

        for (int round = 2; round < 4; round++) {
            int shift = 24 - round * 8;
            unsigned pmask = 0xFFFFFFFFu << (shift + 8);
            for (int i = tid; i < NW * HSEG; i += 1024) {
                int off = i % HSEG;
                if (off < HPAD) whist[i] = 0u;
            }
            __syncthreads();
            unsigned* myh = whist + wid * HSEG;
            if (compacted) {
                for (int i = tid; i < ccnt_pad; i += 1024) {
                    bool inb = (i < ccnt);
                    unsigned u = inb ? s_cand[i] : 0u;
                    bool act = inb && ((u & pmask) == prefix);
                    unsigned bin = (u >> shift) & 255u;
                    unsigned key = act ? bin : 0x100u;
                    unsigned peers = __match_any_sync(0xFFFFFFFFu, key);
                    if (act && lane == (__ffs(peers) - 1)) myh[bin] += __popc(peers);
                }
            } else {
                for (int i = tid; i < A_N; i += 1024) {
                    float v = mv[i];
                    unsigned u = __float_as_uint(v);
                    bool act = (v >= 0.0f) && ((u & pmask) == prefix);
                    unsigned bin = (u >> shift) & 255u;
                    unsigned key = act ? bin : 0x100u;
                    unsigned peers = __match_any_sync(0xFFFFFFFFu, key);
                    if (act && lane == (__ffs(peers) - 1)) myh[bin] += __popc(peers);
                }
            }
            __syncthreads();
            if (tid < 256) {
                unsigned s = 0u;
                #pragma unroll
                for (int w = 0; w < NW; w++) s += whist[w * HSEG + tid];
                suf[tid] = s;
            }
            __syncthreads();
            for (int off = 1; off < 256; off <<= 1) {
                unsigned v = 0;
                if (tid < 256) v = suf[tid] + ((tid + off < 256) ? suf[tid + off] : 0u);
                __syncthreads();
                if (tid < 256) suf[tid] = v;
                __syncthreads();
            }
            if (tid < 256) {
                unsigned below = (tid == 255) ? 0u : suf[tid + 1];
                if (suf[tid] >= (unsigned)rem && below < (unsigned)rem) {
                    s_sel = (unsigned)tid;
                    s_rem = rem - (int)below;
                }
            }
            __syncthreads();
            prefix |= (s_sel << shift);
            rem = s_rem;
            __syncthreads();
        }

        float Tf = __uint_as_float(prefix);
        float ssum; int cgt;
        if (compacted) {
            ssum = gt_sum; cgt = gt_cnt;
            for (int i = tid; i < ccnt; i += 1024) {
                unsigned u = s_cand[i];
                if (u > prefix) { ssum += __uint_as_float(u); cgt++; }
            }
        } else {
            ssum = 0.0f; cgt = 0;
            for (int i = tid; i < A_N; i += 1024) {
                float v = mv[i];
                if (v < 0.0f) continue;
                if (__float_as_uint(v) > prefix) { ssum += v; cgt++; }
            }
        }
        float ws = warp_sum_f(ssum);
        int   wg = warp_sum_i(cgt);
        if (lane == 0) { rs[wid] = ws; rg[wid] = wg; }
        __syncthreads();
        if (wid == 0) {
            float bs = rs[lane];
            int   bgc = rg[lane];
            bs = warp_sum_f(bs); bgc = warp_sum_i(bgc);
            if (lane == 0) g_row_topk[b] = bs + (float)(kk - bgc) * Tf;
        }
    } else {
        if (tid == 0) g_row_topk[b] = 0.0f;
    }

    __syncthreads();
    if (tid == 0) {
        __threadfence();
        unsigned old = atomicAdd(&g_done, 1u);
        s_last = (old == (unsigned)(B_N - 1)) ? 1u : 0u;
    }
    __syncthreads();
    if (s_last) {
        if (tid < 32) {
            int np = g_num_pos_row[tid];
            float tk = g_row_topk[tid];
            np = warp_sum_i(np);
            tk = warp_sum_f(tk);
            if (tid == 0) {
                double denom = fmax(1.0, (double)np) * 4.0;
                out[0] = (float)(g_loc_sum / denom);
                out[1] = (float)((g_ce_sum + (double)tk) / denom);
            }
        }
        for (int i = tid; i < B_N * G_N; i += 1024) g_best_pack[i] = 0ull;
        if (tid < B_N) { g_num_pos_row[tid] = 0; g_row_done[tid] = 0; }
        if (tid == 0) { g_loc_sum = 0.0; g_ce_sum = 0.0; g_done = 0u; }
    }
}

extern "C" void kernel_launch(void* const* d_in, const int* in_sizes, int n_in,
                              void* d_out, int out_size) {
    const float* conf    = (const float*)d_in[0];
    const float* pred    = (const float*)d_in[1];
    const float* gts     = (const float*)d_in[2];
    const int*   counts  = (const int*)d_in[3];
    const float* anchors = (const float*)d_in[4];
    float* out = (float*)d_out;

    cudaFuncSetAttribute(k_topk, cudaFuncAttributeMaxDynamicSharedMemorySize, TOPK_DYN);

    k_match<<<dim3(TILES, B_N), 256>>>(gts, counts, anchors);
    k_main<<<dim3(A_N / 256, B_N), 256>>>(conf, pred, gts, anchors);
    k_topk<<<B_N, 1024, TOPK_DYN>>>(out);
}

// round 17
// speedup vs baseline: 1.1030x; 1.0280x over previous
#include <cuda_runtime.h>
#include <math.h>

#define A_N 32768
#define B_N 32
#define G_N 50
#define C_N 22
#define TILE_A 1024
#define TILES (A_N / TILE_A)   // 32
#define NW 32
#define HPAD 257
#define HSEG (2 * HPAD)
#define CAND_CAP 4096
#define TOPK_DYN ((NW * HSEG + CAND_CAP) * 4)   // 82176 B dynamic
#define CONF_TILE_BYTES (256 * C_N * 4)          // 22528

// ---------------- persistent scratch (zero-init at load; last block re-zeros) --
__device__ unsigned long long g_best_pack[B_N * G_N];  // (iou_bits<<32)|(~a)
__device__ uchar2 g_matchc[B_N * A_N];     // (passed flag, best gt idx); forced stamped
__device__ float  g_mining[B_N * A_N];     // bg_loss for negatives, -1.0f for positives
__device__ int    g_row_done[B_N];
__device__ int    g_num_pos_row[B_N];
__device__ double g_loc_sum;
__device__ double g_ce_sum;
__device__ float  g_row_topk[B_N];
__device__ unsigned g_done;

// ---------------- helpers ----------------
__device__ __forceinline__ float sl1(float d) {
    float ad = fabsf(d);
    return (ad < 1.0f) ? 0.5f * ad * ad : ad - 0.5f;
}
__device__ __forceinline__ float warp_sum_f(float v) {
    #pragma unroll
    for (int o = 16; o; o >>= 1) v += __shfl_down_sync(0xffffffffu, v, o);
    return v;
}
__device__ __forceinline__ int warp_sum_i(int v) {
    #pragma unroll
    for (int o = 16; o; o >>= 1) v += __shfl_down_sync(0xffffffffu, v, o);
    return v;
}
__device__ __forceinline__ float ex2f(float x) {
    float r; asm("ex2.approx.f32 %0, %1;" : "=f"(r) : "f"(x)); return r;
}
__device__ __forceinline__ float lg2f(float x) {
    float r; asm("lg2.approx.f32 %0, %1;" : "=f"(r) : "f"(x)); return r;
}
__device__ __forceinline__ float rcpf(float x) {
    float r; asm("rcp.approx.f32 %0, %1;" : "=f"(r) : "f"(x)); return r;
}
__device__ __forceinline__ unsigned smem_u32(const void* p) {
    unsigned r;
    asm("{ .reg .u64 t; cvta.to.shared.u64 t, %1; cvt.u32.u64 %0, t; }" : "=r"(r) : "l"(p));
    return r;
}

// ---------------- K1: matching (R9 float-compare argmax) + stamping ----------
__global__ void __launch_bounds__(256) k_match(const float* __restrict__ gts,
                                               const int* __restrict__ counts,
                                               const float* __restrict__ anchors) {
    int tile = blockIdx.x, b = blockIdx.y;
    int tid = threadIdx.x;
    int lane = tid & 31;

    __shared__ float4 s_box[G_N];
    __shared__ float  s_areaG[G_N];
    __shared__ unsigned s_fa[G_N];
    __shared__ int s_cnt;
    __shared__ int s_last;
    if (tid == 0) s_cnt = counts[b];
    if (tid < G_N) {
        const float* gp = gts + (size_t)(b * G_N + tid) * 5;
        float x0 = gp[0], y0 = gp[1], x1 = gp[2], y1 = gp[3];
        s_box[tid] = make_float4(x0, y0, x1, y1);
        s_areaG[tid] = (x1 - x0) * (y1 - y0);
    }
    __syncthreads();
    int cnt = s_cnt;

    int base = tile * TILE_A;
    float4 ab[4]; float sA[4]; float best[4]; int bid[4];
    #pragma unroll
    for (int k = 0; k < 4; k++) {
        ab[k] = ((const float4*)anchors)[base + tid + k * 256];
        sA[k] = (ab[k].z - ab[k].x) * (ab[k].w - ab[k].y) + 1e-5f;
        best[k] = 0.0f; bid[k] = 0;
    }

    for (int g = 0; g < cnt; g++) {
        float4 gb = s_box[g];
        float aG = s_areaG[g];
        unsigned lmax = 0u;
        unsigned la = (unsigned)(base + tid);
        #pragma unroll
        for (int k = 0; k < 4; k++) {
            float ltx = fmaxf(gb.x, ab[k].x), lty = fmaxf(gb.y, ab[k].y);
            float rbx = fminf(gb.z, ab[k].z), rby = fminf(gb.w, ab[k].w);
            float w = fmaxf(rbx - ltx, 0.0f), h = fmaxf(rby - lty, 0.0f);
            float inter = w * h;
            float v = inter * rcpf((aG + sA[k]) - inter);       // approx key
            if (v > best[k]) { best[k] = v; bid[k] = g; }       // first-max over g
            unsigned u = __float_as_uint(v);
            if (u > lmax) { lmax = u; la = (unsigned)(base + tid + k * 256); }
        }
        unsigned wmax = __reduce_max_sync(0xffffffffu, lmax);
        unsigned cand = (lmax == wmax) ? la : 0xFFFFFFFFu;
        unsigned amin = __reduce_min_sync(0xffffffffu, cand);
        if (lane == 0)
            atomicMax(&g_best_pack[b * G_N + g],
                      ((unsigned long long)wmax << 32) | (unsigned)(0xFFFFFFFFu - amin));
    }

    // exact IEEE IoU threshold decision for the winning gt; store 2 bytes
    #pragma unroll
    for (int k = 0; k < 4; k++) {
        float4 gb = s_box[bid[k]];
        float aG = s_areaG[bid[k]];
        float ltx = fmaxf(gb.x, ab[k].x), lty = fmaxf(gb.y, ab[k].y);
        float rbx = fminf(gb.z, ab[k].z), rby = fminf(gb.w, ab[k].w);
        float w = fmaxf(rbx - ltx, 0.0f), h = fmaxf(rby - lty, 0.0f);
        float inter = w * h;
        float exact = inter / ((aG + sA[k]) - inter);           // exact IEEE division
        size_t id = (size_t)b * A_N + base + tid + k * 256;
        g_matchc[id] = make_uchar2(exact >= 0.5f ? 1 : 0, (unsigned char)bid[k]);
    }

    // last block of this row stamps forced matches (ascending g, last wins)
    __threadfence();
    __syncthreads();
    if (tid == 0) {
        int old = atomicAdd(&g_row_done[b], 1);
        s_last = (old == TILES - 1) ? 1 : 0;
    }
    __syncthreads();
    if (s_last) {
        if (tid < cnt) {
            unsigned long long p = atomicMax(&g_best_pack[b * G_N + tid], 0ull); // atomic read
            s_fa[tid] = 0xFFFFFFFFu - (unsigned)(p & 0xFFFFFFFFull);
        }
        __syncthreads();
        if (tid == 0) {
            for (int g = 0; g < cnt; g++)
                g_matchc[(size_t)b * A_N + s_fa[g]] = make_uchar2(1, (unsigned char)g);
        }
    }
}

// ---------------- K2: TMA-staged log_softmax + loc loss + pos ce -------------
__global__ void __launch_bounds__(256) k_main(const float* __restrict__ conf,
                                              const float* __restrict__ pred,
                                              const float* __restrict__ gts,
                                              const float* __restrict__ anchors) {
    int b = blockIdx.y;
    int tid = threadIdx.x;
    int a = blockIdx.x * 256 + tid;

    __shared__ alignas(16) float s_conf[256 * C_N];   // 22528 B
    __shared__ float s_gts[G_N * 5];
    __shared__ unsigned long long s_mbar;

    unsigned mbar = smem_u32(&s_mbar);
    if (tid == 0)
        asm volatile("mbarrier.init.shared.b64 [%0], %1;" :: "r"(mbar), "r"(1) : "memory");
    __syncthreads();
    if (tid == 0) {
        asm volatile("mbarrier.arrive.expect_tx.shared.b64 _, [%0], %1;"
                     :: "r"(mbar), "r"((unsigned)CONF_TILE_BYTES) : "memory");
        const float* src = conf + ((size_t)b * A_N + (size_t)blockIdx.x * 256) * C_N;
        asm volatile("cp.async.bulk.shared::cta.global.mbarrier::complete_tx::bytes "
                     "[%0], [%1], %2, [%3];"
                     :: "r"(smem_u32(s_conf)), "l"(src),
                        "r"((unsigned)CONF_TILE_BYTES), "r"(mbar) : "memory");
    }

    for (int i = tid; i < G_N * 5; i += 256)
        s_gts[i] = gts[(size_t)b * G_N * 5 + i];

    size_t idx = (size_t)b * A_N + a;
    uchar2 mt = g_matchc[idx];
    int passed = mt.x;
    int bidx = mt.y;
    __syncthreads();

    int label = passed ? (int)s_gts[bidx * 5 + 4] : 0;
    int is_pos = (label > 0);

    float loc_partial = 0.0f;
    if (is_pos) {
        float4 ab = ((const float4*)anchors)[a];
        float gx0 = s_gts[bidx*5+0], gy0 = s_gts[bidx*5+1];
        float gx1 = s_gts[bidx*5+2], gy1 = s_gts[bidx*5+3];
        float gcx = (gx0 + gx1) * 0.5f, gcy = (gy0 + gy1) * 0.5f;
        float gw  = gx1 - gx0,          gh  = gy1 - gy0;
        float acx = (ab.x + ab.z) * 0.5f, acy = (ab.y + ab.w) * 0.5f;
        float aw  = ab.z - ab.x,          ah  = ab.w - ab.y;
        float t0 = (gcx - acx) / aw / 0.1f;
        float t1 = (gcy - acy) / ah / 0.1f;
        float t2 = logf(fmaxf(gw / aw, 1e-8f)) / 0.2f;
        float t3 = logf(fmaxf(gh / ah, 1e-8f)) / 0.2f;
        float4 p = ((const float4*)pred)[idx];
        loc_partial = sl1(p.x - t0) + sl1(p.y - t1) + sl1(p.z - t2) + sl1(p.w - t3);
    }

    // sleep-hint mbarrier wait (phase 0) — HW-suspends instead of busy-poll
    {
        unsigned done;
        asm volatile("{\n\t.reg .pred p;\n\t"
                     "mbarrier.try_wait.parity.shared.b64 p, [%1], %2;\n\t"
                     "selp.b32 %0, 1, 0, p;\n\t}"
                     : "=r"(done) : "r"(mbar), "r"(0u) : "memory");
        if (!done) {
            asm volatile("{\n\t.reg .pred P1;\n\t"
                         "WAIT_LOOP:\n\t"
                         "mbarrier.try_wait.parity.shared.b64 P1, [%0], %1, 0x989680;\n\t"
                         "@P1 bra.uni WAIT_DONE;\n\t"
                         "bra.uni WAIT_LOOP;\n\t"
                         "WAIT_DONE:\n\t}"
                         :: "r"(mbar), "r"(0u) : "memory");
        }
    }

    const float L2E = 1.4426950408889634f;
    const float LN2 = 0.6931471805599453f;
    const float2* myc2 = (const float2*)(s_conf + tid * C_N);
    float2 v0 = myc2[0];
    float c0 = v0.x;
    float c0L = c0 * L2E;
    float S0 = 1.0f, S1 = ex2f(fmaf(v0.y, L2E, -c0L));
    #pragma unroll
    for (int i = 1; i < 11; i++) {
        float2 v = myc2[i];
        S0 += ex2f(fmaf(v.x, L2E, -c0L));
        S1 += ex2f(fmaf(v.y, L2E, -c0L));
    }
    float bg = lg2f(S0 + S1) * LN2;

    float ce_partial = 0.0f;
    if (is_pos) {
        float clb = s_conf[tid * C_N + label];
        ce_partial = (c0 - clb) + bg;
        g_mining[idx] = -1.0f;
    } else {
        g_mining[idx] = bg;
    }

    float wl = warp_sum_f(loc_partial);
    float wc = warp_sum_f(ce_partial);
    int   wp = warp_sum_i(is_pos);
    __shared__ float rl[8], rc[8];
    __shared__ int   rp[8];
    int lane = tid & 31, wid = tid >> 5;
    if (lane == 0) { rl[wid] = wl; rc[wid] = wc; rp[wid] = wp; }
    __syncthreads();
    if (wid == 0) {
        float bl = (lane < 8) ? rl[lane] : 0.0f;
        float bc = (lane < 8) ? rc[lane] : 0.0f;
        int   bp = (lane < 8) ? rp[lane] : 0;
        bl = warp_sum_f(bl); bc = warp_sum_f(bc); bp = warp_sum_i(bp);
        if (lane == 0) {
            if (bl != 0.0f) atomicAdd(&g_loc_sum, (double)bl);
            if (bc != 0.0f) atomicAdd(&g_ce_sum, (double)bc);
            if (bp != 0)    atomicAdd(&g_num_pos_row[b], bp);
        }
    }
}

// ---------------- K3: radix top-k, float4 dual-histogram first pass -----------
__global__ void __launch_bounds__(1024) k_topk(float* __restrict__ out) {
    extern __shared__ unsigned sdyn_u[];
    unsigned* whist  = sdyn_u;
    unsigned* s_cand = sdyn_u + NW * HSEG;

    __shared__ unsigned suf[256];
    __shared__ unsigned s_sel;
    __shared__ int s_rem;
    __shared__ int s_ccnt;
    __shared__ float rs[32];
    __shared__ int   rg[32];
    __shared__ unsigned s_last;

    int b = blockIdx.x;
    int tid = threadIdx.x;
    int lane = tid & 31;
    int wid = tid >> 5;

    int npos = g_num_pos_row[b];
    int kk = min(3 * npos, A_N - npos);
    const float* mv = g_mining + (size_t)b * A_N;

    if (kk > 0) {
        for (int i = tid; i < NW * HSEG; i += 1024) whist[i] = 0u;
        __syncthreads();
        unsigned* hA = whist + wid * HSEG;
        unsigned* hB = hA + HPAD;
        const float4* mv4 = (const float4*)mv;
        for (int i = tid; i < A_N / 4; i += 1024) {
            float4 q = mv4[i];
            float vv[4] = {q.x, q.y, q.z, q.w};
            #pragma unroll
            for (int c = 0; c < 4; c++) {
                float v = vv[c];
                unsigned u = __float_as_uint(v);
                bool nonneg = (v >= 0.0f);
                unsigned b0 = u >> 24;
                unsigned key0 = nonneg ? b0 : 0x100u;
                unsigned p0 = __match_any_sync(0xFFFFFFFFu, key0);
                if (nonneg && lane == (__ffs(p0) - 1)) hA[b0] += __popc(p0);
                bool c2 = nonneg && (b0 == 0x40u);
                unsigned b1 = (u >> 16) & 255u;
                unsigned key1 = c2 ? b1 : 0x100u;
                unsigned p1 = __match_any_sync(0xFFFFFFFFu, key1);
                if (c2 && lane == (__ffs(p1) - 1)) hB[b1] += __popc(p1);
            }
        }
        __syncthreads();

        int rem = kk;
        if (tid < 256) {
            unsigned s = 0u;
            #pragma unroll
            for (int w = 0; w < NW; w++) s += whist[w * HSEG + tid];
            suf[tid] = s;
        }
        __syncthreads();
        for (int off = 1; off < 256; off <<= 1) {
            unsigned v = 0;
            if (tid < 256) v = suf[tid] + ((tid + off < 256) ? suf[tid + off] : 0u);
            __syncthreads();
            if (tid < 256) suf[tid] = v;
            __syncthreads();
        }
        if (tid < 256) {
            unsigned below = (tid == 255) ? 0u : suf[tid + 1];
            if (suf[tid] >= (unsigned)rem && below < (unsigned)rem) {
                s_sel = (unsigned)tid;
                s_rem = rem - (int)below;
            }
        }
        __syncthreads();
        unsigned t0b = s_sel;
        rem = s_rem;
        __syncthreads();

        if (t0b != 0x40u) {
            for (int i = tid; i < NW * HSEG; i += 1024) {
                int off = i % HSEG;
                if (off >= HPAD) whist[i] = 0u;
            }
            __syncthreads();
            for (int i = tid; i < A_N; i += 1024) {
                float v = mv[i];
                unsigned u = __float_as_uint(v);
                bool act = (v >= 0.0f) && ((u >> 24) == t0b);
                unsigned b1 = (u >> 16) & 255u;
                unsigned key = act ? b1 : 0x100u;
                unsigned p1 = __match_any_sync(0xFFFFFFFFu, key);
                if (act && lane == (__ffs(p1) - 1)) hB[b1] += __popc(p1);
            }
            __syncthreads();
        }
        if (tid < 256) {
            unsigned s = 0u;
            #pragma unroll
            for (int w = 0; w < NW; w++) s += whist[w * HSEG + HPAD + tid];
            suf[tid] = s;
        }
        __syncthreads();
        for (int off = 1; off < 256; off <<= 1) {
            unsigned v = 0;
            if (tid < 256) v = suf[tid] + ((tid + off < 256) ? suf[tid + off] : 0u);
            __syncthreads();
            if (tid < 256) suf[tid] = v;
            __syncthreads();
        }
        if (tid < 256) {
            unsigned below = (tid == 255) ? 0u : suf[tid + 1];
            if (suf[tid] >= (unsigned)rem && below < (unsigned)rem) {
                s_sel = (unsigned)tid;
                s_rem = rem - (int)below;
            }
        }
        __syncthreads();
        unsigned prefix = (t0b << 24) | (s_sel << 16);
        rem = s_rem;
        __syncthreads();

        if (tid == 0) s_ccnt = 0;
        __syncthreads();
        unsigned p16 = prefix >> 16;
        float gt_sum = 0.0f; int gt_cnt = 0;
        for (int i = tid; i < A_N; i += 1024) {
            float v = mv[i];
            unsigned u = __float_as_uint(v);
            bool nonneg = (v >= 0.0f);
            unsigned hi = u >> 16;
            if (nonneg && hi > p16) { gt_sum += v; gt_cnt++; }
            bool iscand = nonneg && (hi == p16);
            unsigned bal = __ballot_sync(0xFFFFFFFFu, iscand);
            if (iscand) {
                int leader = __ffs(bal) - 1;
                int basep = 0;
                if (lane == leader) basep = atomicAdd(&s_ccnt, __popc(bal));
                basep = __shfl_sync(bal, basep, leader);
                int pos = basep + __popc(bal & ((1u << lane) - 1u));
                if (pos < CAND_CAP) s_cand[pos] = u;
            }
        }
        __syncthreads();
        int ccnt = s_ccnt;
        bool compacted = (ccnt <= CAND_CAP);
        int ccnt_pad = (ccnt + 1023) & ~1023;

        for (int round = 2; round < 4; round++) {
            int shift = 24 - round * 8;
            unsigned pmask = 0xFFFFFFFFu << (shift + 8);
            for (int i = tid; i < NW * HSEG; i += 1024) {
                int off = i % HSEG;
                if (off < HPAD) whist[i] = 0u;
            }
            __syncthreads();
            unsigned* myh = whist + wid * HSEG;
            if (compacted) {
                for (int i = tid; i < ccnt_pad; i += 1024) {
                    bool inb = (i < ccnt);
                    unsigned u = inb ? s_cand[i] : 0u;
                    bool act = inb && ((u & pmask) == prefix);
                    unsigned bin = (u >> shift) & 255u;
                    unsigned key = act ? bin : 0x100u;
                    unsigned peers = __match_any_sync(0xFFFFFFFFu, key);
                    if (act && lane == (__ffs(peers) - 1)) myh[bin] += __popc(peers);
                }
            } else {
                for (int i = tid; i < A_N; i += 1024) {
                    float v = mv[i];
                    unsigned u = __float_as_uint(v);
                    bool act = (v >= 0.0f) && ((u & pmask) == prefix);
                    unsigned bin = (u >> shift) & 255u;
                    unsigned key = act ? bin : 0x100u;
                    unsigned peers = __match_any_sync(0xFFFFFFFFu, key);
                    if (act && lane == (__ffs(peers) - 1)) myh[bin] += __popc(peers);
                }
            }
            __syncthreads();
            if (tid < 256) {
                unsigned s = 0u;
                #pragma unroll
                for (int w = 0; w < NW; w++) s += whist[w * HSEG + tid];
                suf[tid] = s;
            }
            __syncthreads();
            for (int off = 1; off < 256; off <<= 1) {
                unsigned v = 0;
                if (tid < 256) v = suf[tid] + ((tid + off < 256) ? suf[tid + off] : 0u);
                __syncthreads();
                if (tid < 256) suf[tid] = v;
                __syncthreads();
            }
            if (tid < 256) {
                unsigned below = (tid == 255) ? 0u : suf[tid + 1];
                if (suf[tid] >= (unsigned)rem && below < (unsigned)rem) {
                    s_sel = (unsigned)tid;
                    s_rem = rem - (int)below;
                }
            }
            __syncthreads();
            prefix |= (s_sel << shift);
            rem = s_rem;
            __syncthreads();
        }

        float Tf = __uint_as_float(prefix);
        float ssum; int cgt;
        if (compacted) {
            ssum = gt_sum; cgt = gt_cnt;
            for (int i = tid; i < ccnt; i += 1024) {
                unsigned u = s_cand[i];
                if (u > prefix) { ssum += __uint_as_float(u); cgt++; }
            }
        } else {
            ssum = 0.0f; cgt = 0;
            for (int i = tid; i < A_N; i += 1024) {
                float v = mv[i];
                if (v < 0.0f) continue;
                if (__float_as_uint(v) > prefix) { ssum += v; cgt++; }
            }
        }
        float ws = warp_sum_f(ssum);
        int   wg = warp_sum_i(cgt);
        if (lane == 0) { rs[wid] = ws; rg[wid] = wg; }
        __syncthreads();
        if (wid == 0) {
            float bs = rs[lane];
            int   bgc = rg[lane];
            bs = warp_sum_f(bs); bgc = warp_sum_i(bgc);
            if (lane == 0) g_row_topk[b] = bs + (float)(kk - bgc) * Tf;
        }
    } else {
        if (tid == 0) g_row_topk[b] = 0.0f;
    }

    __syncthreads();
    if (tid == 0) {
        __threadfence();
        unsigned old = atomicAdd(&g_done, 1u);
        s_last = (old == (unsigned)(B_N - 1)) ? 1u : 0u;
    }
    __syncthreads();
    if (s_last) {
        if (tid < 32) {
            int np = g_num_pos_row[tid];
            float tk = g_row_topk[tid];
            np = warp_sum_i(np);
            tk = warp_sum_f(tk);
            if (tid == 0) {
                double denom = fmax(1.0, (double)np) * 4.0;
                out[0] = (float)(g_loc_sum / denom);
                out[1] = (float)((g_ce_sum + (double)tk) / denom);
            }
        }
        for (int i = tid; i < B_N * G_N; i += 1024) g_best_pack[i] = 0ull;
        if (tid < B_N) { g_num_pos_row[tid] = 0; g_row_done[tid] = 0; }
        if (tid == 0) { g_loc_sum = 0.0; g_ce_sum = 0.0; g_done = 0u; }
    }
}

extern "C" void kernel_launch(void* const* d_in, const int* in_sizes, int n_in,
                              void* d_out, int out_size) {
    const float* conf    = (const float*)d_in[0];
    const float* pred    = (const float*)d_in[1];
    const float* gts     = (const float*)d_in[2];
    const int*   counts  = (const int*)d_in[3];
    const float* anchors = (const float*)d_in[4];
    float* out = (float*)d_out;

    cudaFuncSetAttribute(k_topk, cudaFuncAttributeMaxDynamicSharedMemorySize, TOPK_DYN);

    k_match<<<dim3(TILES, B_N), 256>>>(gts, counts, anchors);
    k_main<<<dim3(A_N / 256, B_N), 256>>>(conf, pred, gts, anchors);
    k_topk<<<B_N, 1024, TOPK_DYN>>>(out);
}